// round 6
// baseline (speedup 1.0000x reference)
#include <cuda_runtime.h>

// ---------------- Problem constants ----------------
#define NB    8
#define SD    512
#define CIN   512
#define COUT  512
#define CPG   64      // channels per group
#define NG    8       // groups
#define HH    64
#define WW    64
#define HWSZ  4096
#define KDK   4608    // 512*9 (im2col K for dk conv)
#define ODK   32768   // C_OUT * 64
#define NCOL  72      // 8 batches * 9 spatial
#define BCOLS 80      // 8 groups * 10 slots (9 valid + 1 pad) for 16B alignment

typedef unsigned long long ull;

// ---------------- Device scratch (no allocs allowed) ----------------
__device__ float g_pooled[NB * SD];                    // 16 KB
__device__ float g_pwkn[NB * ODK];                     // 1 MB
__device__ float g_pwbias[NB * COUT];                  // 16 KB
__device__ __align__(16) ull g_Bdup[KDK * BCOLS];      // 2.95 MB dup-packed im2col of style
__device__ float g_dwT[NB * CPG * 9 * COUT];           // 9.44 MB depthwise weights [n][ci][k][co]

// ---------------- f32x2 helpers (Blackwell packed fp32) ----------------
__device__ __forceinline__ ull pk2(float lo, float hi) {
    ull r;
    asm("mov.b64 %0, {%1, %2};" : "=l"(r) : "f"(lo), "f"(hi));
    return r;
}
__device__ __forceinline__ void upk2(ull v, float& lo, float& hi) {
    asm("mov.b64 {%0, %1}, %2;" : "=f"(lo), "=f"(hi) : "l"(v));
}
__device__ __forceinline__ void fma2(ull& d, ull a, ull b) {
    asm("fma.rn.f32x2 %0, %1, %2, %0;" : "+l"(d) : "l"(a), "l"(b));
}

// ---------------- K0: 3x3 avg pool of style (window at origin) ----------------
__global__ void k_pool(const float* __restrict__ style) {
    int i = blockIdx.x * blockDim.x + threadIdx.x;
    if (i >= NB * SD) return;
    const float* p = style + (size_t)i * 25;
    float s = 0.f;
#pragma unroll
    for (int y = 0; y < 3; y++)
#pragma unroll
        for (int x = 0; x < 3; x++)
            s += p[y * 5 + x];
    g_pooled[i] = s * (1.0f / 9.0f);
}

// ---------------- K0b: build dup-packed im2col B matrix [K][80] ----------------
// Slot layout: group nt occupies slots nt*10 + j, j=0..8 -> (n=nt, spatial q=j); slot j=9 is zero pad.
__global__ void k_buildB(const float* __restrict__ style) {
    int i = blockIdx.x * blockDim.x + threadIdx.x;
    if (i >= KDK * BCOLS) return;
    int k = i / BCOLS, s = i % BCOLS;
    int nt = s / 10, j = s % 10;
    float v = 0.f;
    if (j < 9) {
        int y = j / 3, x = j % 3;
        int sc = k / 9, r = k % 9, dy = r / 3, dx = r % 3;
        v = style[((size_t)(nt * SD + sc) * 5 + (y + dy)) * 5 + (x + dx)];
    }
    g_Bdup[i] = pk2(v, v);
}

// ---------------- K1: pooled GEMVs -> pw_kn (32768 rows) and pw_bias (512 rows) ----------------
__global__ void __launch_bounds__(256) k_pw(const float* __restrict__ Wpwk, const float* __restrict__ bpwk,
                                            const float* __restrict__ Wpwb, const float* __restrict__ bpwb) {
    __shared__ float ps[NB * SD];
    int tid = threadIdx.x;
    for (int i = tid; i < NB * SD; i += 256) ps[i] = g_pooled[i];
    __syncthreads();

    int r = blockIdx.x * 256 + tid;
    if (r >= ODK + COUT) return;
    bool isk = (r < ODK);
    int rr = isk ? r : (r - ODK);
    const float* w = isk ? (Wpwk + (size_t)r * SD) : (Wpwb + (size_t)rr * SD);
    float bias = isk ? bpwk[r] : bpwb[rr];

    float acc[NB];
#pragma unroll
    for (int n = 0; n < NB; n++) acc[n] = 0.f;

    for (int s = 0; s < SD; s += 4) {
        float4 wv = *(const float4*)(w + s);
#pragma unroll
        for (int n = 0; n < NB; n++) {
            const float* pp = &ps[n * SD + s];
            acc[n] += wv.x * pp[0] + wv.y * pp[1] + wv.z * pp[2] + wv.w * pp[3];
        }
    }
    if (isk) {
#pragma unroll
        for (int n = 0; n < NB; n++) g_pwkn[(size_t)n * ODK + r] = acc[n] + bias;
    } else {
#pragma unroll
        for (int n = 0; n < NB; n++) g_pwbias[n * COUT + rr] = acc[n] + bias;
    }
}

// ---------------- K2: dk GEMM (32768 x 72 x 4608), M-paired f32x2 ----------------
// Per block: 64 M-rows. 256 threads = 32 m-groups (1 M-pair each) x 8 n-groups (9 cols each).
#define MTD 64
#define KT  32
#define ASTR 66

__global__ void __launch_bounds__(256) k_dk(const float* __restrict__ Wdk, const float* __restrict__ bdk) {
    __shared__ __align__(16) float As[KT * ASTR];   // 8448 B, [k][m]
    __shared__ __align__(16) ull Bsd[KT * BCOLS];   // 20480 B, dup-packed

    int tid = threadIdx.x;
    int m0 = blockIdx.x * MTD;
    int mt = tid & 31;   // M-pair: rows mt*2, mt*2+1
    int nt = tid >> 5;   // 0..7 -> cols nt*9 .. nt*9+8 (slots nt*10..+8)

    ull acc[9];
#pragma unroll
    for (int j = 0; j < 9; j++) acc[j] = 0ULL;

    int arow = tid >> 2;   // 0..63
    int akq  = tid & 3;    // 0..3
    const float* ap = Wdk + (size_t)(m0 + arow) * KDK + akq * 4;
    float4 pa0 = *(const float4*)(ap);
    float4 pa1 = *(const float4*)(ap + 16);

    for (int k0 = 0; k0 < KDK; k0 += KT) {
        __syncthreads();  // previous tile's compute done before overwriting smem
        // store A tile transposed: k rows akq*4+j (pa0) and 16+akq*4+j (pa1)
        As[(akq * 4 + 0) * ASTR + arow] = pa0.x;
        As[(akq * 4 + 1) * ASTR + arow] = pa0.y;
        As[(akq * 4 + 2) * ASTR + arow] = pa0.z;
        As[(akq * 4 + 3) * ASTR + arow] = pa0.w;
        As[(16 + akq * 4 + 0) * ASTR + arow] = pa1.x;
        As[(16 + akq * 4 + 1) * ASTR + arow] = pa1.y;
        As[(16 + akq * 4 + 2) * ASTR + arow] = pa1.z;
        As[(16 + akq * 4 + 3) * ASTR + arow] = pa1.w;
        // copy dup-packed B tile (L2-resident)
        const ull* bsrc = g_Bdup + (size_t)k0 * BCOLS;
#pragma unroll
        for (int q = 0; q < 10; q++) Bsd[tid + 256 * q] = bsrc[tid + 256 * q];
        // prefetch next A tile while compute runs
        if (k0 + KT < KDK) {
            ap += KT;
            pa0 = *(const float4*)(ap);
            pa1 = *(const float4*)(ap + 16);
        }
        __syncthreads();

#pragma unroll 8
        for (int kk = 0; kk < KT; kk++) {
            ull a = *(const ull*)&As[kk * ASTR + mt * 2];           // M-pair, no packs
            const ull* br = &Bsd[kk * BCOLS + nt * 10];
            ulonglong2 b01 = *(const ulonglong2*)(br);
            ulonglong2 b23 = *(const ulonglong2*)(br + 2);
            ulonglong2 b45 = *(const ulonglong2*)(br + 4);
            ulonglong2 b67 = *(const ulonglong2*)(br + 6);
            ull b8 = br[8];
            fma2(acc[0], a, b01.x);
            fma2(acc[1], a, b01.y);
            fma2(acc[2], a, b23.x);
            fma2(acc[3], a, b23.y);
            fma2(acc[4], a, b45.x);
            fma2(acc[5], a, b45.y);
            fma2(acc[6], a, b67.x);
            fma2(acc[7], a, b67.y);
            fma2(acc[8], a, b8);
        }
    }

    // scatter: acc[j] = rows (m0+mt*2, m0+mt*2+1), col n=nt, kidx=j
    int o0 = m0 + mt * 2;
    float bv0 = bdk[o0], bv1 = bdk[o0 + 1];
    int co = o0 >> 6, ci0 = o0 & 63;   // o0 even -> o0+1 same co, ci0+1
#pragma unroll
    for (int j = 0; j < 9; j++) {
        float lo, hi;
        upk2(acc[j], lo, hi);
        size_t base = ((size_t)((nt * CPG + ci0) * 9 + j)) * COUT + co;
        g_dwT[base] = lo + bv0;
        g_dwT[base + 9 * COUT] = hi + bv1;   // ci0+1
    }
}

// ---------------- K3: fused reflect-pad + depthwise 3x3 + pointwise + bias, f32x2 ----------------
// Block = (rowblock of 4 rows, g, n). 256 threads: thread = (co 0..63, hl 0..3).
// smem: depth tile (64KB) + padded row (in_s) + shifted row (in_sB) + pw weights (16KB).
#define IN_OFF   (CPG * 4 * WW)            // 16384 floats
#define INB_OFF  (IN_OFF + 6 * 68)         // +408
#define PW_OFF   (INB_OFF + 6 * 68)        // +408
#define SMEM_CONV ((PW_OFF + CPG * CPG) * 4)

__device__ __forceinline__ int refl(int i) {
    return i < 0 ? -i : (i > 63 ? 126 - i : i);
}

__global__ void __launch_bounds__(256) k_conv(const float* __restrict__ pred, float* __restrict__ out) {
    extern __shared__ __align__(16) float sm[];
    float* depth_s = sm;                 // [co][hl][w]
    float* in_s  = sm + IN_OFF;          // [6][68]: in_s[r][c] = x[refl(h0+r-1)][refl(c-1)], c<66
    float* in_sB = sm + INB_OFF;         // in_sB[r][c] = in_s[r][c+1], c<65
    float* pw_s  = sm + PW_OFF;          // [cm][co] transposed pw weights

    int tid = threadIdx.x;
    int co = tid & 63;
    int hl = tid >> 6;
    int rb = blockIdx.x, g = blockIdx.y, n = blockIdx.z;
    int h0 = rb * 4;

    const float* base = pred + (size_t)(n * CIN + g * CPG) * HWSZ;

    // preload pw weights transposed (visibility via syncs inside ci loop)
    for (int i = tid; i < CPG * CPG; i += 256) {
        int cm = i >> 6, c = i & 63;
        pw_s[i] = g_pwkn[(size_t)n * ODK + (g * CPG + c) * CPG + cm];
    }

    ull acc2[32];
#pragma unroll
    for (int i = 0; i < 32; i++) acc2[i] = 0ULL;

    for (int ci = 0; ci < CPG; ci++) {
        const float* plane = base + (size_t)ci * HWSZ;
        __syncthreads();  // previous iter's reads of in_s done
        for (int i = tid; i < 6 * 68; i += 256) {
            int r = i / 68, c = i % 68;
            int orow = refl(h0 + r - 1);
            float v = 0.f, vb = 0.f;
            if (c < 66) v = plane[orow * WW + refl(c - 1)];
            if (c < 65) vb = plane[orow * WW + refl(c)];
            in_s[i] = v;
            in_sB[i] = vb;
        }
        __syncthreads();

        // per-thread 3x3 weights for (n, co_global, ci)
        const float* wp = g_dwT + ((size_t)((n * CPG + ci) * 9)) * COUT + (g * CPG + co);
        float d[9];
#pragma unroll
        for (int k = 0; k < 9; k++) d[k] = wp[k * COUT];

#pragma unroll
        for (int kh = 0; kh < 3; kh++) {
            const float* row  = &in_s[(hl + kh) * 68];
            const float* rowB = &in_sB[(hl + kh) * 68];
            ull w0 = pk2(d[kh * 3 + 0], d[kh * 3 + 0]);
            ull w1 = pk2(d[kh * 3 + 1], d[kh * 3 + 1]);
            ull w2 = pk2(d[kh * 3 + 2], d[kh * 3 + 2]);
#pragma unroll
            for (int c0 = 0; c0 < 64; c0 += 16) {
                const ull* ra = (const ull*)(row + c0);
                ulonglong2 a01 = *(const ulonglong2*)(ra);
                ulonglong2 a23 = *(const ulonglong2*)(ra + 2);
                ulonglong2 a45 = *(const ulonglong2*)(ra + 4);
                ulonglong2 a67 = *(const ulonglong2*)(ra + 6);
                ull a8 = ra[8];
                const ull* rbp = (const ull*)(rowB + c0);
                ulonglong2 b01 = *(const ulonglong2*)(rbp);
                ulonglong2 b23 = *(const ulonglong2*)(rbp + 2);
                ulonglong2 b45 = *(const ulonglong2*)(rbp + 4);
                ulonglong2 b67 = *(const ulonglong2*)(rbp + 6);
                int p = c0 >> 1;
                fma2(acc2[p + 0], w0, a01.x); fma2(acc2[p + 0], w1, b01.x); fma2(acc2[p + 0], w2, a01.y);
                fma2(acc2[p + 1], w0, a01.y); fma2(acc2[p + 1], w1, b01.y); fma2(acc2[p + 1], w2, a23.x);
                fma2(acc2[p + 2], w0, a23.x); fma2(acc2[p + 2], w1, b23.x); fma2(acc2[p + 2], w2, a23.y);
                fma2(acc2[p + 3], w0, a23.y); fma2(acc2[p + 3], w1, b23.y); fma2(acc2[p + 3], w2, a45.x);
                fma2(acc2[p + 4], w0, a45.x); fma2(acc2[p + 4], w1, b45.x); fma2(acc2[p + 4], w2, a45.y);
                fma2(acc2[p + 5], w0, a45.y); fma2(acc2[p + 5], w1, b45.y); fma2(acc2[p + 5], w2, a67.x);
                fma2(acc2[p + 6], w0, a67.x); fma2(acc2[p + 6], w1, b67.x); fma2(acc2[p + 6], w2, a67.y);
                fma2(acc2[p + 7], w0, a67.y); fma2(acc2[p + 7], w1, b67.y); fma2(acc2[p + 7], w2, a8);
            }
        }
    }

    // stash depth tile (pairs are contiguous -> u64 stores)
    __syncthreads();
    {
        ull* dst = (ull*)(depth_s + (co * 4 + hl) * 64);
#pragma unroll
        for (int i = 0; i < 32; i++) dst[i] = acc2[i];
    }
    __syncthreads();

    // pointwise: out[co][w] = sum_cm pw[cm][co] * depth[cm][w]
    ull po[32];
#pragma unroll
    for (int i = 0; i < 32; i++) po[i] = 0ULL;
    for (int cm = 0; cm < CPG; cm++) {
        float v = pw_s[cm * 64 + co];
        ull vp = pk2(v, v);
        const ulonglong2* ds = (const ulonglong2*)(depth_s + (cm * 4 + hl) * 64);
#pragma unroll
        for (int i = 0; i < 16; i++) {
            ulonglong2 t = ds[i];
            fma2(po[2 * i],     vp, t.x);
            fma2(po[2 * i + 1], vp, t.y);
        }
    }

    float bias = g_pwbias[n * COUT + g * CPG + co];
    float* op = out + (((size_t)(n * COUT + g * CPG + co)) * HH + (h0 + hl)) * WW;
#pragma unroll
    for (int i = 0; i < 16; i++) {
        float x0, x1, x2, x3;
        upk2(po[2 * i], x0, x1);
        upk2(po[2 * i + 1], x2, x3);
        *(float4*)(op + 4 * i) = make_float4(x0 + bias, x1 + bias, x2 + bias, x3 + bias);
    }
}

// ---------------- Launch ----------------
extern "C" void kernel_launch(void* const* d_in, const int* in_sizes, int n_in,
                              void* d_out, int out_size) {
    const float* style = (const float*)d_in[0];
    const float* pred  = (const float*)d_in[1];
    const float* Wdk   = (const float*)d_in[2];
    const float* bdk   = (const float*)d_in[3];
    const float* Wpwk  = (const float*)d_in[4];
    const float* bpwk  = (const float*)d_in[5];
    const float* Wpwb  = (const float*)d_in[6];
    const float* bpwb  = (const float*)d_in[7];
    float* out = (float*)d_out;

    cudaFuncSetAttribute(k_conv, cudaFuncAttributeMaxDynamicSharedMemorySize, SMEM_CONV);

    k_pool<<<(NB * SD + 255) / 256, 256>>>(style);
    k_buildB<<<(KDK * BCOLS + 255) / 256, 256>>>(style);
    k_pw<<<(ODK + COUT + 255) / 256, 256>>>(Wpwk, bpwk, Wpwb, bpwb);
    k_dk<<<ODK / MTD, 256>>>(Wdk, bdk);
    k_conv<<<dim3(HH / 4, NG, NB), 256, SMEM_CONV>>>(pred, out);
}

// round 7
// speedup vs baseline: 1.2793x; 1.2793x over previous
#include <cuda_runtime.h>

// ---------------- Problem constants ----------------
#define NB    8
#define SD    512
#define CIN   512
#define COUT  512
#define CPG   64
#define NG    8
#define HH    64
#define WW    64
#define HWSZ  4096
#define KDK   4608
#define ODK   32768
#define NCOL  72
#define BCOLS 80      // 8 groups * 10 slots (9 valid + 1 pad)

typedef unsigned long long ull;

// ---------------- Device scratch ----------------
__device__ float g_pooled[NB * SD];
__device__ float g_pwkn[NB * ODK];
__device__ float g_pwbias[NB * COUT];
__device__ __align__(16) ull g_Bdup[KDK * BCOLS];      // dup-packed im2col of style
__device__ float g_dwT[NB * CPG * 9 * COUT];           // [n][ci][k][co]

// ---------------- f32x2 helpers ----------------
__device__ __forceinline__ ull pk2(float lo, float hi) {
    ull r;
    asm("mov.b64 %0, {%1, %2};" : "=l"(r) : "f"(lo), "f"(hi));
    return r;
}
__device__ __forceinline__ void upk2(ull v, float& lo, float& hi) {
    asm("mov.b64 {%0, %1}, %2;" : "=f"(lo), "=f"(hi) : "l"(v));
}
__device__ __forceinline__ void fma2(ull& d, ull a, ull b) {
    asm("fma.rn.f32x2 %0, %1, %2, %0;" : "+l"(d) : "l"(a), "l"(b));
}

// ---------------- K0: 3x3 avg pool ----------------
__global__ void k_pool(const float* __restrict__ style) {
    int i = blockIdx.x * blockDim.x + threadIdx.x;
    if (i >= NB * SD) return;
    const float* p = style + (size_t)i * 25;
    float s = 0.f;
#pragma unroll
    for (int y = 0; y < 3; y++)
#pragma unroll
        for (int x = 0; x < 3; x++)
            s += p[y * 5 + x];
    g_pooled[i] = s * (1.0f / 9.0f);
}

// ---------------- K0b: build dup-packed im2col B [K][80] ----------------
__global__ void k_buildB(const float* __restrict__ style) {
    int i = blockIdx.x * blockDim.x + threadIdx.x;
    if (i >= KDK * BCOLS) return;
    int k = i / BCOLS, s = i % BCOLS;
    int nt = s / 10, j = s % 10;
    float v = 0.f;
    if (j < 9) {
        int y = j / 3, x = j % 3;
        int sc = k / 9, r = k % 9, dy = r / 3, dx = r % 3;
        v = style[((size_t)(nt * SD + sc) * 5 + (y + dy)) * 5 + (x + dx)];
    }
    g_Bdup[i] = pk2(v, v);
}

// ---------------- K1: pooled GEMVs ----------------
__global__ void __launch_bounds__(256) k_pw(const float* __restrict__ Wpwk, const float* __restrict__ bpwk,
                                            const float* __restrict__ Wpwb, const float* __restrict__ bpwb) {
    __shared__ float ps[NB * SD];
    int tid = threadIdx.x;
    for (int i = tid; i < NB * SD; i += 256) ps[i] = g_pooled[i];
    __syncthreads();

    int r = blockIdx.x * 256 + tid;
    if (r >= ODK + COUT) return;
    bool isk = (r < ODK);
    int rr = isk ? r : (r - ODK);
    const float* w = isk ? (Wpwk + (size_t)r * SD) : (Wpwb + (size_t)rr * SD);
    float bias = isk ? bpwk[r] : bpwb[rr];

    float acc[NB];
#pragma unroll
    for (int n = 0; n < NB; n++) acc[n] = 0.f;

    for (int s = 0; s < SD; s += 4) {
        float4 wv = *(const float4*)(w + s);
#pragma unroll
        for (int n = 0; n < NB; n++) {
            const float* pp = &ps[n * SD + s];
            acc[n] += wv.x * pp[0] + wv.y * pp[1] + wv.z * pp[2] + wv.w * pp[3];
        }
    }
    if (isk) {
#pragma unroll
        for (int n = 0; n < NB; n++) g_pwkn[(size_t)n * ODK + r] = acc[n] + bias;
    } else {
#pragma unroll
        for (int n = 0; n < NB; n++) g_pwbias[n * COUT + rr] = acc[n] + bias;
    }
}

// ---------------- K2: dk GEMM (32768 x 72 x 4608), 4 rows x 9 cols per thread ----------------
#define MTD 128
#define KT  32
#define ASTR 132

__global__ void __launch_bounds__(256) k_dk(const float* __restrict__ Wdk, const float* __restrict__ bdk) {
    __shared__ __align__(16) float As[KT * ASTR];   // [k][m], 16896 B
    __shared__ __align__(16) ull Bsd[KT * BCOLS];   // 20480 B

    int tid = threadIdx.x;
    int m0 = blockIdx.x * MTD;
    int mt = tid & 31;   // row quad: mt*4 .. mt*4+3 (two pairs)
    int nt = tid >> 5;   // 0..7 -> 9 cols

    ull acc[2][9];
#pragma unroll
    for (int i = 0; i < 2; i++)
#pragma unroll
        for (int j = 0; j < 9; j++) acc[i][j] = 0ULL;

    int arow = tid >> 1;          // 0..127
    int kbase = (tid & 1) * 16;   // 0 or 16
    const float* ap = Wdk + (size_t)(m0 + arow) * KDK + kbase;
    float4 pa[4];
#pragma unroll
    for (int q = 0; q < 4; q++) pa[q] = *(const float4*)(ap + q * 4);

    for (int k0 = 0; k0 < KDK; k0 += KT) {
        __syncthreads();  // previous tile compute done
        // store A tile transposed
#pragma unroll
        for (int q = 0; q < 4; q++) {
            int k = kbase + q * 4;
            As[(k + 0) * ASTR + arow] = pa[q].x;
            As[(k + 1) * ASTR + arow] = pa[q].y;
            As[(k + 2) * ASTR + arow] = pa[q].z;
            As[(k + 3) * ASTR + arow] = pa[q].w;
        }
        // copy dup-packed B tile (L2-resident)
        const ull* bsrc = g_Bdup + (size_t)k0 * BCOLS;
#pragma unroll
        for (int q = 0; q < 10; q++) Bsd[tid + 256 * q] = bsrc[tid + 256 * q];
        // prefetch next A tile
        if (k0 + KT < KDK) {
            ap += KT;
#pragma unroll
            for (int q = 0; q < 4; q++) pa[q] = *(const float4*)(ap + q * 4);
        }
        __syncthreads();

#pragma unroll 8
        for (int kk = 0; kk < KT; kk++) {
            ulonglong2 av = *(const ulonglong2*)&As[kk * ASTR + mt * 4];  // two M-pairs
            const ull* br = &Bsd[kk * BCOLS + nt * 10];
            ulonglong2 b01 = *(const ulonglong2*)(br);
            ulonglong2 b23 = *(const ulonglong2*)(br + 2);
            ulonglong2 b45 = *(const ulonglong2*)(br + 4);
            ulonglong2 b67 = *(const ulonglong2*)(br + 6);
            ull b8 = br[8];
            fma2(acc[0][0], av.x, b01.x); fma2(acc[1][0], av.y, b01.x);
            fma2(acc[0][1], av.x, b01.y); fma2(acc[1][1], av.y, b01.y);
            fma2(acc[0][2], av.x, b23.x); fma2(acc[1][2], av.y, b23.x);
            fma2(acc[0][3], av.x, b23.y); fma2(acc[1][3], av.y, b23.y);
            fma2(acc[0][4], av.x, b45.x); fma2(acc[1][4], av.y, b45.x);
            fma2(acc[0][5], av.x, b45.y); fma2(acc[1][5], av.y, b45.y);
            fma2(acc[0][6], av.x, b67.x); fma2(acc[1][6], av.y, b67.x);
            fma2(acc[0][7], av.x, b67.y); fma2(acc[1][7], av.y, b67.y);
            fma2(acc[0][8], av.x, b8);    fma2(acc[1][8], av.y, b8);
        }
    }

    // scatter: pair i covers rows o0+2i, o0+2i+1 ; col group n=nt, kidx=j
    int o0 = m0 + mt * 4;
    int co = o0 >> 6, ci0 = o0 & 63;   // quad stays inside one co
#pragma unroll
    for (int i = 0; i < 2; i++) {
        float bv0 = bdk[o0 + 2 * i], bv1 = bdk[o0 + 2 * i + 1];
#pragma unroll
        for (int j = 0; j < 9; j++) {
            float lo, hi;
            upk2(acc[i][j], lo, hi);
            size_t base = ((size_t)((nt * CPG + ci0 + 2 * i) * 9 + j)) * COUT + co;
            g_dwT[base] = lo + bv0;
            g_dwT[base + 9 * COUT] = hi + bv1;
        }
    }
}

// ---------------- K3: fused depthwise+pointwise, double-buffered prefetch ----------------
#define IN_OFF   (CPG * 4 * WW)                 // 16384 floats (depth tile)
#define BUFSZ    816                            // (408 main + 408 shifted) per buffer
#define PW_OFF   (IN_OFF + 2 * BUFSZ)           // + 1632
#define SMEM_CONV ((PW_OFF + CPG * CPG) * 4)    // 88448 B

__device__ __forceinline__ int refl(int i) {
    return i < 0 ? -i : (i > 63 ? 126 - i : i);
}

__global__ void __launch_bounds__(256) k_conv(const float* __restrict__ pred, float* __restrict__ out) {
    extern __shared__ __align__(16) float sm[];
    float* depth_s = sm;
    float* in_base = sm + IN_OFF;   // two buffers of [408 main | 408 shifted]
    float* pw_s    = sm + PW_OFF;

    int tid = threadIdx.x;
    int co = tid & 63;
    int hl = tid >> 6;
    int rb = blockIdx.x, g = blockIdx.y, n = blockIdx.z;
    int h0 = rb * 4;

    const float* base = pred + (size_t)(n * CIN + g * CPG) * HWSZ;

    // preload pw weights transposed (visible after first barrier)
    for (int i = tid; i < CPG * CPG; i += 256) {
        int cm = i >> 6, c = i & 63;
        pw_s[i] = g_pwkn[(size_t)n * ODK + (g * CPG + c) * CPG + cm];
    }

    // loader geometry: positions idx in [0, 396): r = idx/66, c = idx%66
    int i0 = tid, i1 = tid + 256;
    int r0 = i0 / 66, c0p = i0 % 66;
    int r1 = i1 / 66, c1p = i1 % 66;
    bool v1 = (i1 < 396);
    int goff0 = refl(h0 + r0 - 1) * WW + refl(c0p - 1);
    int goff1 = v1 ? (refl(h0 + r1 - 1) * WW + refl(c1p - 1)) : 0;
    int s0 = r0 * 68 + c0p;
    int s1 = r1 * 68 + c1p;

    // prefetch ci=0 input + weights
    float q0 = base[goff0];
    float q1 = v1 ? base[goff1] : 0.f;
    const float* wp = g_dwT + ((size_t)(n * CPG) * 9) * COUT + (g * CPG + co);
    float dcur[9], dnxt[9];
#pragma unroll
    for (int k = 0; k < 9; k++) dcur[k] = wp[k * COUT];

    ull acc2[32];
#pragma unroll
    for (int i = 0; i < 32; i++) acc2[i] = 0ULL;

    for (int ci = 0; ci < CPG; ci++) {
        float* ia = in_base + (ci & 1) * BUFSZ;
        float* ib = ia + 408;
        ia[s0] = q0;
        if (c0p) ib[s0 - 1] = q0;
        if (v1) {
            ia[s1] = q1;
            if (c1p) ib[s1 - 1] = q1;
        }
        __syncthreads();

        // prefetch ci+1 input + weights (overlaps compute)
        if (ci + 1 < CPG) {
            const float* pl = base + (size_t)(ci + 1) * HWSZ;
            q0 = pl[goff0];
            q1 = v1 ? pl[goff1] : 0.f;
            const float* wn = wp + (size_t)(ci + 1) * 9 * COUT;
#pragma unroll
            for (int k = 0; k < 9; k++) dnxt[k] = wn[k * COUT];
        }

        // compute depthwise for this ci
#pragma unroll
        for (int kh = 0; kh < 3; kh++) {
            const float* row  = &ia[(hl + kh) * 68];
            const float* rowB = row + 408;
            ull w0 = pk2(dcur[kh * 3 + 0], dcur[kh * 3 + 0]);
            ull w1 = pk2(dcur[kh * 3 + 1], dcur[kh * 3 + 1]);
            ull w2 = pk2(dcur[kh * 3 + 2], dcur[kh * 3 + 2]);
#pragma unroll
            for (int c0 = 0; c0 < 64; c0 += 16) {
                const ull* ra = (const ull*)(row + c0);
                ulonglong2 a01 = *(const ulonglong2*)(ra);
                ulonglong2 a23 = *(const ulonglong2*)(ra + 2);
                ulonglong2 a45 = *(const ulonglong2*)(ra + 4);
                ulonglong2 a67 = *(const ulonglong2*)(ra + 6);
                ull a8 = ra[8];
                const ull* rbp = (const ull*)(rowB + c0);
                ulonglong2 b01 = *(const ulonglong2*)(rbp);
                ulonglong2 b23 = *(const ulonglong2*)(rbp + 2);
                ulonglong2 b45 = *(const ulonglong2*)(rbp + 4);
                ulonglong2 b67 = *(const ulonglong2*)(rbp + 6);
                int p = c0 >> 1;
                fma2(acc2[p + 0], w0, a01.x); fma2(acc2[p + 0], w1, b01.x); fma2(acc2[p + 0], w2, a01.y);
                fma2(acc2[p + 1], w0, a01.y); fma2(acc2[p + 1], w1, b01.y); fma2(acc2[p + 1], w2, a23.x);
                fma2(acc2[p + 2], w0, a23.x); fma2(acc2[p + 2], w1, b23.x); fma2(acc2[p + 2], w2, a23.y);
                fma2(acc2[p + 3], w0, a23.y); fma2(acc2[p + 3], w1, b23.y); fma2(acc2[p + 3], w2, a45.x);
                fma2(acc2[p + 4], w0, a45.x); fma2(acc2[p + 4], w1, b45.x); fma2(acc2[p + 4], w2, a45.y);
                fma2(acc2[p + 5], w0, a45.y); fma2(acc2[p + 5], w1, b45.y); fma2(acc2[p + 5], w2, a67.x);
                fma2(acc2[p + 6], w0, a67.x); fma2(acc2[p + 6], w1, b67.x); fma2(acc2[p + 6], w2, a67.y);
                fma2(acc2[p + 7], w0, a67.y); fma2(acc2[p + 7], w1, b67.y); fma2(acc2[p + 7], w2, a8);
            }
        }
#pragma unroll
        for (int k = 0; k < 9; k++) dcur[k] = dnxt[k];
    }

    // stash depth tile
    __syncthreads();
    {
        ull* dst = (ull*)(depth_s + (co * 4 + hl) * 64);
#pragma unroll
        for (int i = 0; i < 32; i++) dst[i] = acc2[i];
    }
    __syncthreads();

    // pointwise (reuse acc2 as output accumulator)
#pragma unroll
    for (int i = 0; i < 32; i++) acc2[i] = 0ULL;
    for (int cm = 0; cm < CPG; cm++) {
        float v = pw_s[cm * 64 + co];
        ull vp = pk2(v, v);
        const ulonglong2* ds = (const ulonglong2*)(depth_s + (cm * 4 + hl) * 64);
#pragma unroll
        for (int i = 0; i < 16; i++) {
            ulonglong2 t = ds[i];
            fma2(acc2[2 * i],     vp, t.x);
            fma2(acc2[2 * i + 1], vp, t.y);
        }
    }

    float bias = g_pwbias[n * COUT + g * CPG + co];
    float* op = out + (((size_t)(n * COUT + g * CPG + co)) * HH + (h0 + hl)) * WW;
#pragma unroll
    for (int i = 0; i < 16; i++) {
        float x0, x1, x2, x3;
        upk2(acc2[2 * i], x0, x1);
        upk2(acc2[2 * i + 1], x2, x3);
        *(float4*)(op + 4 * i) = make_float4(x0 + bias, x1 + bias, x2 + bias, x3 + bias);
    }
}

// ---------------- Launch ----------------
extern "C" void kernel_launch(void* const* d_in, const int* in_sizes, int n_in,
                              void* d_out, int out_size) {
    const float* style = (const float*)d_in[0];
    const float* pred  = (const float*)d_in[1];
    const float* Wdk   = (const float*)d_in[2];
    const float* bdk   = (const float*)d_in[3];
    const float* Wpwk  = (const float*)d_in[4];
    const float* bpwk  = (const float*)d_in[5];
    const float* Wpwb  = (const float*)d_in[6];
    const float* bpwb  = (const float*)d_in[7];
    float* out = (float*)d_out;

    cudaFuncSetAttribute(k_conv, cudaFuncAttributeMaxDynamicSharedMemorySize, SMEM_CONV);

    k_pool<<<(NB * SD + 255) / 256, 256>>>(style);
    k_buildB<<<(KDK * BCOLS + 255) / 256, 256>>>(style);
    k_pw<<<(ODK + COUT + 255) / 256, 256>>>(Wpwk, bpwk, Wpwb, bpwb);
    k_dk<<<ODK / MTD, 256>>>(Wdk, bdk);
    k_conv<<<dim3(HH / 4, NG, NB), 256, SMEM_CONV>>>(pred, out);
}